// round 1
// baseline (speedup 1.0000x reference)
#include <cuda_runtime.h>
#include <cuda_bf16.h>
#include <math.h>

// Problem constants
#define N_NODES 50000
#define N_EDGES 800000
#define CH 128
#define OUT_CH 6
#define N_GRAPHS 64
#define MAX_DEG 96

// ---------------- static device scratch (no allocation allowed) ----------------
__device__ int   g_is64;                       // 1 if indices are int64
__device__ int   g_src[N_EDGES];
__device__ int   g_dst[N_EDGES];
__device__ int   g_batch[N_NODES];
__device__ int   g_cursor[N_NODES];            // becomes in-degree after fill
__device__ float g_dinv[N_NODES];
__device__ int   g_bucket[(size_t)N_NODES * MAX_DEG];
__device__ float g_G[(size_t)N_NODES * CH];    // g = dinv * (in @ W)
__device__ float g_H[(size_t)N_NODES * CH];    // layer output
__device__ float g_H6[(size_t)N_NODES * OUT_CH];

// ---------------- dtype detection ----------------
// If edge_index is int64 (values < 2^31, little endian), every odd 32-bit word
// is zero. If int32, odd words are random node ids in [0,50000) -> essentially
// never all zero across 128 samples.
__global__ void detect_kernel(const unsigned int* __restrict__ ei_words) {
    __shared__ int nonzero;
    if (threadIdx.x == 0) nonzero = 0;
    __syncthreads();
    // check odd words 1,3,...,255
    int idx = 2 * threadIdx.x + 1;   // threadIdx.x in [0,128)
    if (ei_words[idx] != 0u) atomicOr(&nonzero, 1);
    __syncthreads();
    if (threadIdx.x == 0) g_is64 = nonzero ? 0 : 1;
}

__device__ __forceinline__ int read_idx(const void* p, long long i, int is64) {
    if (is64) return (int)((const long long*)p)[i];
    return ((const int*)p)[i];
}

__global__ void convert_edges_kernel(const void* __restrict__ edge_index) {
    int is64 = g_is64;
    for (int e = blockIdx.x * blockDim.x + threadIdx.x; e < N_EDGES;
         e += gridDim.x * blockDim.x) {
        g_src[e] = read_idx(edge_index, e, is64);
        g_dst[e] = read_idx(edge_index, (long long)N_EDGES + e, is64);
    }
}

__global__ void prep_nodes_kernel(const void* __restrict__ batch) {
    int is64 = g_is64;
    for (int i = blockIdx.x * blockDim.x + threadIdx.x; i < N_NODES;
         i += gridDim.x * blockDim.x) {
        g_batch[i]  = read_idx(batch, i, is64);
        g_cursor[i] = 0;
    }
}

// ---------------- CSR bucket build ----------------
__global__ void fill_edges_kernel() {
    for (int e = blockIdx.x * blockDim.x + threadIdx.x; e < N_EDGES;
         e += gridDim.x * blockDim.x) {
        int d = g_dst[e];
        int pos = atomicAdd(&g_cursor[d], 1);
        if (pos < MAX_DEG) g_bucket[(size_t)d * MAX_DEG + pos] = g_src[e];
    }
}

__global__ void dinv_kernel() {
    for (int i = blockIdx.x * blockDim.x + threadIdx.x; i < N_NODES;
         i += gridDim.x * blockDim.x) {
        g_dinv[i] = rsqrtf((float)g_cursor[i] + 1.0f);
    }
}

// ---------------- GEMM: G = dinv .* (A @ W),  A:[M,128], W:[128,128] ----------------
// Classic 128x128 tile, BK=8, 256 threads, 8x8 per thread.
__global__ __launch_bounds__(256, 2)
void gemm_kernel(const float* __restrict__ A, const float* __restrict__ W,
                 float* __restrict__ G) {
    __shared__ float As[8][128];
    __shared__ float Bs[8][128];
    const int tid = threadIdx.x;
    const int block_row = blockIdx.x * 128;
    const int ty = tid >> 4;          // 0..15
    const int tx = tid & 15;          // 0..15

    const int arow = tid >> 1;        // 0..127
    const int acol = (tid & 1) * 4;   // 0 or 4
    const int brow = tid >> 5;        // 0..7
    const int bcol = (tid & 31) * 4;  // 0..124

    float acc[8][8];
#pragma unroll
    for (int i = 0; i < 8; i++)
#pragma unroll
        for (int j = 0; j < 8; j++) acc[i][j] = 0.0f;

    int grow = block_row + arow;
    if (grow >= N_NODES) grow = N_NODES - 1;   // clamp; store is guarded
    const float* Aptr = A + (size_t)grow * CH;

    for (int k0 = 0; k0 < CH; k0 += 8) {
        float4 av = *(const float4*)(Aptr + k0 + acol);
        As[acol + 0][arow] = av.x;
        As[acol + 1][arow] = av.y;
        As[acol + 2][arow] = av.z;
        As[acol + 3][arow] = av.w;
        float4 bv = *(const float4*)(W + (size_t)(k0 + brow) * CH + bcol);
        *(float4*)&Bs[brow][bcol] = bv;
        __syncthreads();
#pragma unroll
        for (int kk = 0; kk < 8; kk++) {
            float4 a0 = *(const float4*)&As[kk][ty * 8];
            float4 a1 = *(const float4*)&As[kk][ty * 8 + 4];
            float4 b0 = *(const float4*)&Bs[kk][tx * 8];
            float4 b1 = *(const float4*)&Bs[kk][tx * 8 + 4];
            float a[8] = {a0.x, a0.y, a0.z, a0.w, a1.x, a1.y, a1.z, a1.w};
            float b[8] = {b0.x, b0.y, b0.z, b0.w, b1.x, b1.y, b1.z, b1.w};
#pragma unroll
            for (int i = 0; i < 8; i++)
#pragma unroll
                for (int j = 0; j < 8; j++) acc[i][j] = fmaf(a[i], b[j], acc[i][j]);
        }
        __syncthreads();
    }

#pragma unroll
    for (int i = 0; i < 8; i++) {
        int row = block_row + ty * 8 + i;
        if (row < N_NODES) {
            float s = g_dinv[row];
            float4 o0 = make_float4(acc[i][0] * s, acc[i][1] * s, acc[i][2] * s, acc[i][3] * s);
            float4 o1 = make_float4(acc[i][4] * s, acc[i][5] * s, acc[i][6] * s, acc[i][7] * s);
            *(float4*)(G + (size_t)row * CH + tx * 8)     = o0;
            *(float4*)(G + (size_t)row * CH + tx * 8 + 4) = o1;
        }
    }
}

// ---------------- Aggregation: H[i] = tanh(dinv[i]*(G[i] + sum_j G[src_j]) + b) ----------------
// one warp per node, lane handles 4 channels (float4)
__global__ __launch_bounds__(256)
void agg_kernel(const float* __restrict__ b, float* __restrict__ H) {
    const int lane = threadIdx.x & 31;
    const int warp = (blockIdx.x * blockDim.x + threadIdx.x) >> 5;
    if (warp >= N_NODES) return;
    const int i = warp;

    const float* grow = g_G + (size_t)i * CH + lane * 4;
    float4 acc = *(const float4*)grow;

    int deg = g_cursor[i];
    if (deg > MAX_DEG) deg = MAX_DEG;
    const int* bk = g_bucket + (size_t)i * MAX_DEG;

    int j = 0;
    // unroll by 4 for memory-level parallelism
    for (; j + 4 <= deg; j += 4) {
        int s0 = bk[j], s1 = bk[j + 1], s2 = bk[j + 2], s3 = bk[j + 3];
        float4 v0 = *(const float4*)(g_G + (size_t)s0 * CH + lane * 4);
        float4 v1 = *(const float4*)(g_G + (size_t)s1 * CH + lane * 4);
        float4 v2 = *(const float4*)(g_G + (size_t)s2 * CH + lane * 4);
        float4 v3 = *(const float4*)(g_G + (size_t)s3 * CH + lane * 4);
        acc.x += v0.x + v1.x + v2.x + v3.x;
        acc.y += v0.y + v1.y + v2.y + v3.y;
        acc.z += v0.z + v1.z + v2.z + v3.z;
        acc.w += v0.w + v1.w + v2.w + v3.w;
    }
    for (; j < deg; j++) {
        int s = bk[j];
        float4 v = *(const float4*)(g_G + (size_t)s * CH + lane * 4);
        acc.x += v.x; acc.y += v.y; acc.z += v.z; acc.w += v.w;
    }

    float dv = g_dinv[i];
    float4 bb = *(const float4*)(b + lane * 4);
    float4 o;
    o.x = tanhf(fmaf(dv, acc.x, bb.x));
    o.y = tanhf(fmaf(dv, acc.y, bb.y));
    o.z = tanhf(fmaf(dv, acc.z, bb.z));
    o.w = tanhf(fmaf(dv, acc.w, bb.w));
    *(float4*)(H + (size_t)i * CH + lane * 4) = o;
}

// ---------------- Head: H6 = tanh(H @ Wl + bl), Wl:[128,6] ----------------
__global__ __launch_bounds__(256)
void head_kernel(const float* __restrict__ H, const float* __restrict__ Wl,
                 const float* __restrict__ bl) {
    const int lane = threadIdx.x & 31;
    const int node = (blockIdx.x * blockDim.x + threadIdx.x) >> 5;
    if (node >= N_NODES) return;
    float4 h = *(const float4*)(H + (size_t)node * CH + lane * 4);
    int k = lane * 4;
#pragma unroll
    for (int c = 0; c < OUT_CH; c++) {
        float p = h.x * Wl[(k + 0) * OUT_CH + c]
                + h.y * Wl[(k + 1) * OUT_CH + c]
                + h.z * Wl[(k + 2) * OUT_CH + c]
                + h.w * Wl[(k + 3) * OUT_CH + c];
#pragma unroll
        for (int off = 16; off > 0; off >>= 1)
            p += __shfl_xor_sync(0xffffffffu, p, off);
        if (lane == 0) g_H6[(size_t)node * OUT_CH + c] = tanhf(p + bl[c]);
    }
}

// ---------------- Pool: per-graph mean over sorted batch ----------------
__global__ __launch_bounds__(256)
void pool_kernel(float* __restrict__ out) {
    const int g = blockIdx.x;
    __shared__ int s_lo, s_hi;
    __shared__ float ssum[OUT_CH];
    if (threadIdx.x == 0) {
        // lower_bound(batch, g) and lower_bound(batch, g+1)
        int lo = 0, hi = N_NODES;
        while (lo < hi) { int m = (lo + hi) >> 1; if (g_batch[m] < g) lo = m + 1; else hi = m; }
        s_lo = lo;
        int lo2 = lo, hi2 = N_NODES;
        while (lo2 < hi2) { int m = (lo2 + hi2) >> 1; if (g_batch[m] < g + 1) lo2 = m + 1; else hi2 = m; }
        s_hi = lo2;
    }
    if (threadIdx.x < OUT_CH) ssum[threadIdx.x] = 0.0f;
    __syncthreads();
    int lo = s_lo, hi = s_hi;
    float loc[OUT_CH];
#pragma unroll
    for (int c = 0; c < OUT_CH; c++) loc[c] = 0.0f;
    for (int i = lo + threadIdx.x; i < hi; i += blockDim.x) {
#pragma unroll
        for (int c = 0; c < OUT_CH; c++) loc[c] += g_H6[(size_t)i * OUT_CH + c];
    }
    // warp reduce then shared atomics (few)
#pragma unroll
    for (int c = 0; c < OUT_CH; c++) {
#pragma unroll
        for (int off = 16; off > 0; off >>= 1)
            loc[c] += __shfl_xor_sync(0xffffffffu, loc[c], off);
    }
    if ((threadIdx.x & 31) == 0) {
#pragma unroll
        for (int c = 0; c < OUT_CH; c++) atomicAdd(&ssum[c], loc[c]);
    }
    __syncthreads();
    if (threadIdx.x < OUT_CH) {
        float cnt = (float)(hi - lo);
        if (cnt < 1.0f) cnt = 1.0f;
        out[g * OUT_CH + threadIdx.x] = ssum[threadIdx.x] / cnt;
    }
}

// ---------------- launch ----------------
extern "C" void kernel_launch(void* const* d_in, const int* in_sizes, int n_in,
                              void* d_out, int out_size) {
    const float* x   = (const float*)d_in[0];
    const void*  ei  = d_in[1];
    const void*  bat = d_in[2];
    const float* W0  = (const float*)d_in[3];
    const float* b0  = (const float*)d_in[4];
    const float* W1  = (const float*)d_in[5];
    const float* b1  = (const float*)d_in[6];
    const float* W2  = (const float*)d_in[7];
    const float* b2  = (const float*)d_in[8];
    const float* Wl  = (const float*)d_in[9];
    const float* bl  = (const float*)d_in[10];
    float* out = (float*)d_out;

    // resolve device symbol addresses for kernels needing raw pointers
    float *Gp, *Hp;
    cudaGetSymbolAddress((void**)&Gp, g_G);
    cudaGetSymbolAddress((void**)&Hp, g_H);

    detect_kernel<<<1, 128>>>((const unsigned int*)ei);
    prep_nodes_kernel<<<(N_NODES + 255) / 256, 256>>>(bat);
    convert_edges_kernel<<<(N_EDGES + 255) / 256, 256>>>(ei);
    fill_edges_kernel<<<(N_EDGES + 255) / 256, 256>>>();
    dinv_kernel<<<(N_NODES + 255) / 256, 256>>>();

    const int gemm_grid = (N_NODES + 127) / 128;
    const int agg_grid  = (N_NODES * 32 + 255) / 256;   // 8 warps/block

    // layer 0: x -> G -> H
    gemm_kernel<<<gemm_grid, 256>>>(x, W0, Gp);
    agg_kernel<<<agg_grid, 256>>>(b0, Hp);
    // layer 1: H -> G -> H
    gemm_kernel<<<gemm_grid, 256>>>(Hp, W1, Gp);
    agg_kernel<<<agg_grid, 256>>>(b1, Hp);
    // layer 2
    gemm_kernel<<<gemm_grid, 256>>>(Hp, W2, Gp);
    agg_kernel<<<agg_grid, 256>>>(b2, Hp);

    head_kernel<<<(N_NODES * 32 + 255) / 256, 256>>>(Hp, Wl, bl);
    pool_kernel<<<N_GRAPHS, 256>>>(out);
}

// round 3
// speedup vs baseline: 1.1311x; 1.1311x over previous
#include <cuda_runtime.h>
#include <cuda_bf16.h>
#include <math.h>
#include <stdint.h>
#include <cstdint>

// Problem constants
#define N_NODES 50000
#define N_EDGES 800000
#define CH 128
#define OUT_CH 6
#define N_GRAPHS 64
#define MAX_DEG 96

#define ASTRIDE 136   // As[k][m] pad -> conflict-free frag loads
#define WSTRIDE 132   // Ws[n][k] pad -> conflict-free frag loads
#define GEMM_SMEM_BYTES ((128 * ASTRIDE + 128 * WSTRIDE) * 4)

// ---------------- static device scratch (no allocation allowed) ----------------
__device__ int   g_is64;
__device__ int   g_src[N_EDGES];
__device__ int   g_dst[N_EDGES];
__device__ int   g_batch[N_NODES];
__device__ int   g_cursor[N_NODES];            // becomes in-degree after fill
__device__ float g_dinv[N_NODES];
__device__ int   g_bucket[(size_t)N_NODES * MAX_DEG];
__device__ float g_G[(size_t)N_NODES * CH];    // g = dinv * (in @ W)
__device__ float g_H[(size_t)N_NODES * CH];    // layer output
__device__ float g_H6[(size_t)N_NODES * OUT_CH];

// ---------------- dtype detection ----------------
__global__ void detect_kernel(const unsigned int* __restrict__ ei_words) {
    __shared__ int nonzero;
    if (threadIdx.x == 0) nonzero = 0;
    __syncthreads();
    int idx = 2 * threadIdx.x + 1;   // odd words of first 128 int64s
    if (ei_words[idx] != 0u) atomicOr(&nonzero, 1);
    __syncthreads();
    if (threadIdx.x == 0) g_is64 = nonzero ? 0 : 1;
}

__device__ __forceinline__ int read_idx(const void* p, long long i, int is64) {
    if (is64) return (int)((const long long*)p)[i];
    return ((const int*)p)[i];
}

// convert edges + batch + zero cursors, one kernel
__global__ void convprep_kernel(const void* __restrict__ edge_index,
                                const void* __restrict__ batch) {
    int is64 = g_is64;
    for (int e = blockIdx.x * blockDim.x + threadIdx.x; e < N_EDGES;
         e += gridDim.x * blockDim.x) {
        g_src[e] = read_idx(edge_index, e, is64);
        g_dst[e] = read_idx(edge_index, (long long)N_EDGES + e, is64);
    }
    for (int i = blockIdx.x * blockDim.x + threadIdx.x; i < N_NODES;
         i += gridDim.x * blockDim.x) {
        g_batch[i]  = read_idx(batch, i, is64);
        g_cursor[i] = 0;
    }
}

__global__ void fill_edges_kernel() {
    for (int e = blockIdx.x * blockDim.x + threadIdx.x; e < N_EDGES;
         e += gridDim.x * blockDim.x) {
        int d = g_dst[e];
        int pos = atomicAdd(&g_cursor[d], 1);
        if (pos < MAX_DEG) g_bucket[(size_t)d * MAX_DEG + pos] = g_src[e];
    }
}

__global__ void dinv_kernel() {
    for (int i = blockIdx.x * blockDim.x + threadIdx.x; i < N_NODES;
         i += gridDim.x * blockDim.x) {
        g_dinv[i] = rsqrtf((float)g_cursor[i] + 1.0f);
    }
}

// ---------------- tf32 tensor-core GEMM: G = dinv .* (A @ W) ----------------
// CTA: 256 threads (8 warps, 4x2 M/N warp grid), tile 128x128, full K=128 in smem.
__device__ __forceinline__ uint32_t f2tf32(float f) {
    uint32_t u;
    asm("cvt.rna.tf32.f32 %0, %1;" : "=r"(u) : "f"(f));
    return u;
}

__global__ __launch_bounds__(256, 1)
void gemm_tf32_kernel(const float* __restrict__ A, const float* __restrict__ W,
                      float* __restrict__ G) {
    extern __shared__ float smem[];
    float* As = smem;                       // [k:128][m:ASTRIDE]
    float* Ws = smem + 128 * ASTRIDE;       // [n:128][k:WSTRIDE]

    const int tid = threadIdx.x;
    const int block_row = blockIdx.x * 128;

    // Load A tile (transposed k-major, tf32-converted)
#pragma unroll
    for (int it = 0; it < 16; it++) {
        int idx = tid + it * 256;           // 4096 float4s
        int m = idx >> 5;
        int k = (idx & 31) << 2;
        int gm = block_row + m;
        if (gm >= N_NODES) gm = N_NODES - 1;
        float4 v = *(const float4*)(A + (size_t)gm * CH + k);
        As[(k + 0) * ASTRIDE + m] = __uint_as_float(f2tf32(v.x));
        As[(k + 1) * ASTRIDE + m] = __uint_as_float(f2tf32(v.y));
        As[(k + 2) * ASTRIDE + m] = __uint_as_float(f2tf32(v.z));
        As[(k + 3) * ASTRIDE + m] = __uint_as_float(f2tf32(v.w));
    }
    // Load W (transposed n-major, tf32-converted)
#pragma unroll
    for (int it = 0; it < 16; it++) {
        int idx = tid + it * 256;
        int k = idx >> 5;
        int n = (idx & 31) << 2;
        float4 v = *(const float4*)(W + (size_t)k * CH + n);
        Ws[(n + 0) * WSTRIDE + k] = __uint_as_float(f2tf32(v.x));
        Ws[(n + 1) * WSTRIDE + k] = __uint_as_float(f2tf32(v.y));
        Ws[(n + 2) * WSTRIDE + k] = __uint_as_float(f2tf32(v.z));
        Ws[(n + 3) * WSTRIDE + k] = __uint_as_float(f2tf32(v.w));
    }
    __syncthreads();

    const int lane = tid & 31;
    const int warp = tid >> 5;
    const int wm = (warp & 3) * 32;         // 4 warps along M
    const int wn = (warp >> 2) * 64;        // 2 warps along N

    float c[2][8][4];
#pragma unroll
    for (int mt = 0; mt < 2; mt++)
#pragma unroll
        for (int nt = 0; nt < 8; nt++)
#pragma unroll
            for (int q = 0; q < 4; q++) c[mt][nt][q] = 0.0f;

    const int lq = lane >> 2;               // 0..7
    const int lr = lane & 3;                // 0..3

#pragma unroll
    for (int ks = 0; ks < 16; ks++) {
        const int k0 = ks * 8;
        uint32_t a[2][4];
#pragma unroll
        for (int mt = 0; mt < 2; mt++) {
            int r = wm + mt * 16 + lq;
            int kc = k0 + lr;
            a[mt][0] = __float_as_uint(As[kc * ASTRIDE + r]);
            a[mt][1] = __float_as_uint(As[kc * ASTRIDE + r + 8]);
            a[mt][2] = __float_as_uint(As[(kc + 4) * ASTRIDE + r]);
            a[mt][3] = __float_as_uint(As[(kc + 4) * ASTRIDE + r + 8]);
        }
#pragma unroll
        for (int nt = 0; nt < 8; nt++) {
            int nc = wn + nt * 8 + lq;
            int kc = k0 + lr;
            uint32_t b0 = __float_as_uint(Ws[nc * WSTRIDE + kc]);
            uint32_t b1 = __float_as_uint(Ws[nc * WSTRIDE + kc + 4]);
#pragma unroll
            for (int mt = 0; mt < 2; mt++) {
                asm volatile(
                    "mma.sync.aligned.m16n8k8.row.col.f32.tf32.tf32.f32 "
                    "{%0,%1,%2,%3}, {%4,%5,%6,%7}, {%8,%9}, {%0,%1,%2,%3};"
                    : "+f"(c[mt][nt][0]), "+f"(c[mt][nt][1]),
                      "+f"(c[mt][nt][2]), "+f"(c[mt][nt][3])
                    : "r"(a[mt][0]), "r"(a[mt][1]), "r"(a[mt][2]), "r"(a[mt][3]),
                      "r"(b0), "r"(b1));
            }
        }
    }

    // Epilogue: scale by dinv[row], store float2 pairs
#pragma unroll
    for (int mt = 0; mt < 2; mt++) {
        int r0 = block_row + wm + mt * 16 + lq;
        int r1 = r0 + 8;
        if (r0 < N_NODES) {
            float s = g_dinv[r0];
#pragma unroll
            for (int nt = 0; nt < 8; nt++) {
                float2 o = make_float2(c[mt][nt][0] * s, c[mt][nt][1] * s);
                *(float2*)(G + (size_t)r0 * CH + wn + nt * 8 + lr * 2) = o;
            }
        }
        if (r1 < N_NODES) {
            float s = g_dinv[r1];
#pragma unroll
            for (int nt = 0; nt < 8; nt++) {
                float2 o = make_float2(c[mt][nt][2] * s, c[mt][nt][3] * s);
                *(float2*)(G + (size_t)r1 * CH + wn + nt * 8 + lr * 2) = o;
            }
        }
    }
}

// ---------------- Aggregation (optionally fused with head for last layer) ----------------
template <bool LAST>
__global__ __launch_bounds__(256)
void agg_kernel_t(const float* __restrict__ b, float* __restrict__ H,
                  const float* __restrict__ Wl, const float* __restrict__ bl) {
    const int lane = threadIdx.x & 31;
    const int warp = (blockIdx.x * blockDim.x + threadIdx.x) >> 5;
    if (warp >= N_NODES) return;
    const int i = warp;

    const float* grow = g_G + (size_t)i * CH + lane * 4;
    float4 acc = *(const float4*)grow;

    int deg = g_cursor[i];
    if (deg > MAX_DEG) deg = MAX_DEG;
    const int* bk = g_bucket + (size_t)i * MAX_DEG;

    int j = 0;
    for (; j + 4 <= deg; j += 4) {
        int s0 = bk[j], s1 = bk[j + 1], s2 = bk[j + 2], s3 = bk[j + 3];
        float4 v0 = *(const float4*)(g_G + (size_t)s0 * CH + lane * 4);
        float4 v1 = *(const float4*)(g_G + (size_t)s1 * CH + lane * 4);
        float4 v2 = *(const float4*)(g_G + (size_t)s2 * CH + lane * 4);
        float4 v3 = *(const float4*)(g_G + (size_t)s3 * CH + lane * 4);
        acc.x += v0.x + v1.x + v2.x + v3.x;
        acc.y += v0.y + v1.y + v2.y + v3.y;
        acc.z += v0.z + v1.z + v2.z + v3.z;
        acc.w += v0.w + v1.w + v2.w + v3.w;
    }
    for (; j < deg; j++) {
        int s = bk[j];
        float4 v = *(const float4*)(g_G + (size_t)s * CH + lane * 4);
        acc.x += v.x; acc.y += v.y; acc.z += v.z; acc.w += v.w;
    }

    float dv = g_dinv[i];
    float4 bb = *(const float4*)(b + lane * 4);
    float4 o;
    o.x = tanhf(fmaf(dv, acc.x, bb.x));
    o.y = tanhf(fmaf(dv, acc.y, bb.y));
    o.z = tanhf(fmaf(dv, acc.z, bb.z));
    o.w = tanhf(fmaf(dv, acc.w, bb.w));

    if (!LAST) {
        *(float4*)(H + (size_t)i * CH + lane * 4) = o;
    } else {
        // fused head: H6 = tanh(h @ Wl + bl)
        int k = lane * 4;
#pragma unroll
        for (int cidx = 0; cidx < OUT_CH; cidx++) {
            float p = o.x * Wl[(k + 0) * OUT_CH + cidx]
                    + o.y * Wl[(k + 1) * OUT_CH + cidx]
                    + o.z * Wl[(k + 2) * OUT_CH + cidx]
                    + o.w * Wl[(k + 3) * OUT_CH + cidx];
#pragma unroll
            for (int off = 16; off > 0; off >>= 1)
                p += __shfl_xor_sync(0xffffffffu, p, off);
            if (lane == 0) g_H6[(size_t)i * OUT_CH + cidx] = tanhf(p + bl[cidx]);
        }
    }
}

// ---------------- Pool: per-graph mean over sorted batch ----------------
__global__ __launch_bounds__(256)
void pool_kernel(float* __restrict__ out) {
    const int g = blockIdx.x;
    __shared__ int s_lo, s_hi;
    __shared__ float ssum[OUT_CH];
    if (threadIdx.x == 0) {
        int lo = 0, hi = N_NODES;
        while (lo < hi) { int m = (lo + hi) >> 1; if (g_batch[m] < g) lo = m + 1; else hi = m; }
        s_lo = lo;
        int lo2 = lo, hi2 = N_NODES;
        while (lo2 < hi2) { int m = (lo2 + hi2) >> 1; if (g_batch[m] < g + 1) lo2 = m + 1; else hi2 = m; }
        s_hi = lo2;
    }
    if (threadIdx.x < OUT_CH) ssum[threadIdx.x] = 0.0f;
    __syncthreads();
    int lo = s_lo, hi = s_hi;
    float loc[OUT_CH];
#pragma unroll
    for (int c = 0; c < OUT_CH; c++) loc[c] = 0.0f;
    for (int i = lo + threadIdx.x; i < hi; i += blockDim.x) {
#pragma unroll
        for (int c = 0; c < OUT_CH; c++) loc[c] += g_H6[(size_t)i * OUT_CH + c];
    }
#pragma unroll
    for (int c = 0; c < OUT_CH; c++) {
#pragma unroll
        for (int off = 16; off > 0; off >>= 1)
            loc[c] += __shfl_xor_sync(0xffffffffu, loc[c], off);
    }
    if ((threadIdx.x & 31) == 0) {
#pragma unroll
        for (int c = 0; c < OUT_CH; c++) atomicAdd(&ssum[c], loc[c]);
    }
    __syncthreads();
    if (threadIdx.x < OUT_CH) {
        float cnt = (float)(hi - lo);
        if (cnt < 1.0f) cnt = 1.0f;
        out[g * OUT_CH + threadIdx.x] = ssum[threadIdx.x] / cnt;
    }
}

// ---------------- launch ----------------
extern "C" void kernel_launch(void* const* d_in, const int* in_sizes, int n_in,
                              void* d_out, int out_size) {
    const float* x   = (const float*)d_in[0];
    const void*  ei  = d_in[1];
    const void*  bat = d_in[2];
    const float* W0  = (const float*)d_in[3];
    const float* b0  = (const float*)d_in[4];
    const float* W1  = (const float*)d_in[5];
    const float* b1  = (const float*)d_in[6];
    const float* W2  = (const float*)d_in[7];
    const float* b2  = (const float*)d_in[8];
    const float* Wl  = (const float*)d_in[9];
    const float* bl  = (const float*)d_in[10];
    float* out = (float*)d_out;

    float *Gp, *Hp;
    cudaGetSymbolAddress((void**)&Gp, g_G);
    cudaGetSymbolAddress((void**)&Hp, g_H);

    cudaFuncSetAttribute(gemm_tf32_kernel,
                         cudaFuncAttributeMaxDynamicSharedMemorySize,
                         GEMM_SMEM_BYTES);

    detect_kernel<<<1, 128>>>((const unsigned int*)ei);
    convprep_kernel<<<(N_EDGES + 255) / 256, 256>>>(ei, bat);
    fill_edges_kernel<<<(N_EDGES + 255) / 256, 256>>>();
    dinv_kernel<<<(N_NODES + 255) / 256, 256>>>();

    const int gemm_grid = (N_NODES + 127) / 128;   // 391
    const int agg_grid  = (N_NODES * 32 + 255) / 256;

    gemm_tf32_kernel<<<gemm_grid, 256, GEMM_SMEM_BYTES>>>(x, W0, Gp);
    agg_kernel_t<false><<<agg_grid, 256>>>(b0, Hp, Wl, bl);
    gemm_tf32_kernel<<<gemm_grid, 256, GEMM_SMEM_BYTES>>>(Hp, W1, Gp);
    agg_kernel_t<false><<<agg_grid, 256>>>(b1, Hp, Wl, bl);
    gemm_tf32_kernel<<<gemm_grid, 256, GEMM_SMEM_BYTES>>>(Hp, W2, Gp);
    agg_kernel_t<true><<<agg_grid, 256>>>(b2, Hp, Wl, bl);

    pool_kernel<<<N_GRAPHS, 256>>>(out);
}

// round 4
// speedup vs baseline: 1.6157x; 1.4285x over previous
#include <cuda_runtime.h>
#include <cuda_bf16.h>
#include <math.h>
#include <stdint.h>
#include <cstdint>

// Problem constants
#define N_NODES 50000
#define N_EDGES 800000
#define CH 128
#define OUT_CH 6
#define N_GRAPHS 64
#define MAX_DEG 96

// GEMM tile config: M=64, N=128, K=128 (full K in smem)
#define TILE_M 64
#define AST 132     // As[m][k] row stride (words); 132%4==0 (f4 aligned), loads bank = lq*4+lr
#define WST 136     // Ws[k][n] row stride (words); 136%32==8 -> B loads bank = lr*8+lq
#define GEMM_SMEM_BYTES ((TILE_M * AST + 128 * WST) * 4)

// ---------------- static device scratch (no allocation allowed) ----------------
__device__ int   g_is64;
__device__ int   g_batch[N_NODES];
__device__ int   g_cursor[N_NODES];            // in-degree after fill
__device__ float g_dinv[N_NODES];
__device__ int   g_bucket[(size_t)N_NODES * MAX_DEG];
__device__ float g_G[(size_t)N_NODES * CH];    // G = A @ W   (unscaled)
__device__ float g_H[(size_t)N_NODES * CH];    // layer output
__device__ float g_H6[(size_t)N_NODES * OUT_CH];

// ---------------- zero cursors + dtype detect (one kernel) ----------------
__global__ void zero_detect_kernel(const unsigned int* __restrict__ ei_words) {
    int i = blockIdx.x * blockDim.x + threadIdx.x;
    if (i < N_NODES) g_cursor[i] = 0;
    if (blockIdx.x == 0) {
        __shared__ int nonzero;
        if (threadIdx.x == 0) nonzero = 0;
        __syncthreads();
        if (threadIdx.x < 128) {
            int idx = 2 * threadIdx.x + 1;   // odd words of first 128 int64s
            if (ei_words[idx] != 0u) atomicOr(&nonzero, 1);
        }
        __syncthreads();
        if (threadIdx.x == 0) g_is64 = nonzero ? 0 : 1;
    }
}

__device__ __forceinline__ int read_idx(const void* p, long long i, int is64) {
    if (is64) return (int)((const long long*)p)[i];
    return ((const int*)p)[i];
}

// convert edges -> bucket CSR directly, plus batch conversion
__global__ void convfill_kernel(const void* __restrict__ edge_index,
                                const void* __restrict__ batch) {
    int is64 = g_is64;
    for (int e = blockIdx.x * blockDim.x + threadIdx.x; e < N_EDGES;
         e += gridDim.x * blockDim.x) {
        int s = read_idx(edge_index, e, is64);
        int d = read_idx(edge_index, (long long)N_EDGES + e, is64);
        int pos = atomicAdd(&g_cursor[d], 1);
        if (pos < MAX_DEG) g_bucket[(size_t)d * MAX_DEG + pos] = s;
    }
    for (int i = blockIdx.x * blockDim.x + threadIdx.x; i < N_NODES;
         i += gridDim.x * blockDim.x) {
        g_batch[i] = read_idx(batch, i, is64);
    }
}

__global__ void dinv_kernel() {
    for (int i = blockIdx.x * blockDim.x + threadIdx.x; i < N_NODES;
         i += gridDim.x * blockDim.x) {
        g_dinv[i] = rsqrtf((float)g_cursor[i] + 1.0f);
    }
}

// ---------------- tf32 tensor-core GEMM: G = A @ W  (no scaling) ----------------
__device__ __forceinline__ uint32_t f2tf32(float f) {
    uint32_t u;
    asm("cvt.rna.tf32.f32 %0, %1;" : "=r"(u) : "f"(f));
    return u;
}

__global__ __launch_bounds__(256)
void gemm_tf32_kernel(const float* __restrict__ A, const float* __restrict__ W,
                      float* __restrict__ G) {
    extern __shared__ float smem[];
    float* As = smem;                     // [m:TILE_M][k: AST]
    float* Ws = smem + TILE_M * AST;      // [k:128][n: WST]

    const int tid = threadIdx.x;
    const int block_row = blockIdx.x * TILE_M;

    // Load A tile row-major (conflict-free float4 stores), tf32-convert
#pragma unroll
    for (int it = 0; it < 8; it++) {
        int idx = tid + it * 256;         // 2048 float4s (64 x 128 floats)
        int m = idx >> 5;
        int k = (idx & 31) << 2;
        int gm = block_row + m;
        if (gm >= N_NODES) gm = N_NODES - 1;    // clamp; stores guarded later
        float4 v = *(const float4*)(A + (size_t)gm * CH + k);
        float4 t;
        t.x = __uint_as_float(f2tf32(v.x));
        t.y = __uint_as_float(f2tf32(v.y));
        t.z = __uint_as_float(f2tf32(v.z));
        t.w = __uint_as_float(f2tf32(v.w));
        *(float4*)&As[m * AST + k] = t;
    }
    // Load W row-major (as in gmem: W[k][n]) — no transpose needed
#pragma unroll
    for (int it = 0; it < 16; it++) {
        int idx = tid + it * 256;         // 4096 float4s (128 x 128 floats)
        int k = idx >> 5;
        int n = (idx & 31) << 2;
        float4 v = *(const float4*)(W + (size_t)k * CH + n);
        float4 t;
        t.x = __uint_as_float(f2tf32(v.x));
        t.y = __uint_as_float(f2tf32(v.y));
        t.z = __uint_as_float(f2tf32(v.z));
        t.w = __uint_as_float(f2tf32(v.w));
        *(float4*)&Ws[k * WST + n] = t;
    }
    __syncthreads();

    const int lane = tid & 31;
    const int warp = tid >> 5;
    const int wm = (warp & 1) * 32;       // 2 warps along M (32 rows each)
    const int wn = (warp >> 1) * 32;      // 4 warps along N (32 cols each)

    const int lq = lane >> 2;             // 0..7
    const int lr = lane & 3;              // 0..3

    float c[2][4][4];
#pragma unroll
    for (int mt = 0; mt < 2; mt++)
#pragma unroll
        for (int nt = 0; nt < 4; nt++)
#pragma unroll
            for (int q = 0; q < 4; q++) c[mt][nt][q] = 0.0f;

#pragma unroll
    for (int ks = 0; ks < 16; ks++) {
        const int k0 = ks * 8;
        uint32_t a[2][4];
#pragma unroll
        for (int mt = 0; mt < 2; mt++) {
            int r = wm + mt * 16 + lq;
            // A frag (m16 x k8): rows r, r+8; cols k0+lr, k0+lr+4
            a[mt][0] = __float_as_uint(As[r * AST + k0 + lr]);
            a[mt][1] = __float_as_uint(As[(r + 8) * AST + k0 + lr]);
            a[mt][2] = __float_as_uint(As[r * AST + k0 + lr + 4]);
            a[mt][3] = __float_as_uint(As[(r + 8) * AST + k0 + lr + 4]);
        }
#pragma unroll
        for (int nt = 0; nt < 4; nt++) {
            int nc = wn + nt * 8 + lq;
            // B frag (k8 x n8): b0 = W[k0+lr][nc], b1 = W[k0+lr+4][nc]
            uint32_t b0 = __float_as_uint(Ws[(k0 + lr) * WST + nc]);
            uint32_t b1 = __float_as_uint(Ws[(k0 + lr + 4) * WST + nc]);
#pragma unroll
            for (int mt = 0; mt < 2; mt++) {
                asm volatile(
                    "mma.sync.aligned.m16n8k8.row.col.f32.tf32.tf32.f32 "
                    "{%0,%1,%2,%3}, {%4,%5,%6,%7}, {%8,%9}, {%0,%1,%2,%3};"
                    : "+f"(c[mt][nt][0]), "+f"(c[mt][nt][1]),
                      "+f"(c[mt][nt][2]), "+f"(c[mt][nt][3])
                    : "r"(a[mt][0]), "r"(a[mt][1]), "r"(a[mt][2]), "r"(a[mt][3]),
                      "r"(b0), "r"(b1));
            }
        }
    }

    // Epilogue: plain store (no dinv — applied in agg)
#pragma unroll
    for (int mt = 0; mt < 2; mt++) {
        int r0 = block_row + wm + mt * 16 + lq;
        int r1 = r0 + 8;
        if (r0 < N_NODES) {
#pragma unroll
            for (int nt = 0; nt < 4; nt++) {
                float2 o = make_float2(c[mt][nt][0], c[mt][nt][1]);
                *(float2*)(G + (size_t)r0 * CH + wn + nt * 8 + lr * 2) = o;
            }
        }
        if (r1 < N_NODES) {
#pragma unroll
            for (int nt = 0; nt < 4; nt++) {
                float2 o = make_float2(c[mt][nt][2], c[mt][nt][3]);
                *(float2*)(G + (size_t)r1 * CH + wn + nt * 8 + lr * 2) = o;
            }
        }
    }
}

// ---------------- Aggregation: H[i] = tanh(dv_i*(dv_i*G_i + sum_j dv_j*G_j) + b) ----------------
template <bool LAST>
__global__ __launch_bounds__(256)
void agg_kernel_t(const float* __restrict__ b, float* __restrict__ H,
                  const float* __restrict__ Wl, const float* __restrict__ bl) {
    const int lane = threadIdx.x & 31;
    const int warp = (blockIdx.x * blockDim.x + threadIdx.x) >> 5;
    if (warp >= N_NODES) return;
    const int i = warp;

    float dv = g_dinv[i];

    float4 self = __ldg((const float4*)(g_G + (size_t)i * CH + lane * 4));
    float4 acc;
    acc.x = self.x * dv; acc.y = self.y * dv; acc.z = self.z * dv; acc.w = self.w * dv;

    int deg = g_cursor[i];
    if (deg > MAX_DEG) deg = MAX_DEG;
    const int* bk = g_bucket + (size_t)i * MAX_DEG;

    int j = 0;
    for (; j + 4 <= deg; j += 4) {
        int s0 = __ldg(bk + j);
        int s1 = __ldg(bk + j + 1);
        int s2 = __ldg(bk + j + 2);
        int s3 = __ldg(bk + j + 3);
        float d0 = __ldg(g_dinv + s0);
        float d1 = __ldg(g_dinv + s1);
        float d2 = __ldg(g_dinv + s2);
        float d3 = __ldg(g_dinv + s3);
        float4 v0 = __ldg((const float4*)(g_G + (size_t)s0 * CH + lane * 4));
        float4 v1 = __ldg((const float4*)(g_G + (size_t)s1 * CH + lane * 4));
        float4 v2 = __ldg((const float4*)(g_G + (size_t)s2 * CH + lane * 4));
        float4 v3 = __ldg((const float4*)(g_G + (size_t)s3 * CH + lane * 4));
        acc.x = fmaf(v0.x, d0, fmaf(v1.x, d1, fmaf(v2.x, d2, fmaf(v3.x, d3, acc.x))));
        acc.y = fmaf(v0.y, d0, fmaf(v1.y, d1, fmaf(v2.y, d2, fmaf(v3.y, d3, acc.y))));
        acc.z = fmaf(v0.z, d0, fmaf(v1.z, d1, fmaf(v2.z, d2, fmaf(v3.z, d3, acc.z))));
        acc.w = fmaf(v0.w, d0, fmaf(v1.w, d1, fmaf(v2.w, d2, fmaf(v3.w, d3, acc.w))));
    }
    for (; j < deg; j++) {
        int s = __ldg(bk + j);
        float ds = __ldg(g_dinv + s);
        float4 v = __ldg((const float4*)(g_G + (size_t)s * CH + lane * 4));
        acc.x = fmaf(v.x, ds, acc.x);
        acc.y = fmaf(v.y, ds, acc.y);
        acc.z = fmaf(v.z, ds, acc.z);
        acc.w = fmaf(v.w, ds, acc.w);
    }

    float4 bb = *(const float4*)(b + lane * 4);
    float4 o;
    o.x = tanhf(fmaf(dv, acc.x, bb.x));
    o.y = tanhf(fmaf(dv, acc.y, bb.y));
    o.z = tanhf(fmaf(dv, acc.z, bb.z));
    o.w = tanhf(fmaf(dv, acc.w, bb.w));

    if (!LAST) {
        *(float4*)(H + (size_t)i * CH + lane * 4) = o;
    } else {
        // fused head: H6 = tanh(h @ Wl + bl)
        int k = lane * 4;
#pragma unroll
        for (int cidx = 0; cidx < OUT_CH; cidx++) {
            float p = o.x * Wl[(k + 0) * OUT_CH + cidx]
                    + o.y * Wl[(k + 1) * OUT_CH + cidx]
                    + o.z * Wl[(k + 2) * OUT_CH + cidx]
                    + o.w * Wl[(k + 3) * OUT_CH + cidx];
#pragma unroll
            for (int off = 16; off > 0; off >>= 1)
                p += __shfl_xor_sync(0xffffffffu, p, off);
            if (lane == 0) g_H6[(size_t)i * OUT_CH + cidx] = tanhf(p + bl[cidx]);
        }
    }
}

// ---------------- Pool: per-graph mean over sorted batch ----------------
__global__ __launch_bounds__(256)
void pool_kernel(float* __restrict__ out) {
    const int g = blockIdx.x;
    __shared__ int s_lo, s_hi;
    __shared__ float ssum[OUT_CH];
    if (threadIdx.x == 0) {
        int lo = 0, hi = N_NODES;
        while (lo < hi) { int m = (lo + hi) >> 1; if (g_batch[m] < g) lo = m + 1; else hi = m; }
        s_lo = lo;
        int lo2 = lo, hi2 = N_NODES;
        while (lo2 < hi2) { int m = (lo2 + hi2) >> 1; if (g_batch[m] < g + 1) lo2 = m + 1; else hi2 = m; }
        s_hi = lo2;
    }
    if (threadIdx.x < OUT_CH) ssum[threadIdx.x] = 0.0f;
    __syncthreads();
    int lo = s_lo, hi = s_hi;
    float loc[OUT_CH];
#pragma unroll
    for (int c = 0; c < OUT_CH; c++) loc[c] = 0.0f;
    for (int i = lo + threadIdx.x; i < hi; i += blockDim.x) {
#pragma unroll
        for (int c = 0; c < OUT_CH; c++) loc[c] += g_H6[(size_t)i * OUT_CH + c];
    }
#pragma unroll
    for (int c = 0; c < OUT_CH; c++) {
#pragma unroll
        for (int off = 16; off > 0; off >>= 1)
            loc[c] += __shfl_xor_sync(0xffffffffu, loc[c], off);
    }
    if ((threadIdx.x & 31) == 0) {
#pragma unroll
        for (int c = 0; c < OUT_CH; c++) atomicAdd(&ssum[c], loc[c]);
    }
    __syncthreads();
    if (threadIdx.x < OUT_CH) {
        float cnt = (float)(hi - lo);
        if (cnt < 1.0f) cnt = 1.0f;
        out[g * OUT_CH + threadIdx.x] = ssum[threadIdx.x] / cnt;
    }
}

// ---------------- launch ----------------
extern "C" void kernel_launch(void* const* d_in, const int* in_sizes, int n_in,
                              void* d_out, int out_size) {
    const float* x   = (const float*)d_in[0];
    const void*  ei  = d_in[1];
    const void*  bat = d_in[2];
    const float* W0  = (const float*)d_in[3];
    const float* b0  = (const float*)d_in[4];
    const float* W1  = (const float*)d_in[5];
    const float* b1  = (const float*)d_in[6];
    const float* W2  = (const float*)d_in[7];
    const float* b2  = (const float*)d_in[8];
    const float* Wl  = (const float*)d_in[9];
    const float* bl  = (const float*)d_in[10];
    float* out = (float*)d_out;

    float *Gp, *Hp;
    cudaGetSymbolAddress((void**)&Gp, g_G);
    cudaGetSymbolAddress((void**)&Hp, g_H);

    cudaFuncSetAttribute(gemm_tf32_kernel,
                         cudaFuncAttributeMaxDynamicSharedMemorySize,
                         GEMM_SMEM_BYTES);

    zero_detect_kernel<<<(N_NODES + 255) / 256, 256>>>((const unsigned int*)ei);
    convfill_kernel<<<(N_EDGES + 255) / 256, 256>>>(ei, bat);
    dinv_kernel<<<(N_NODES + 255) / 256, 256>>>();

    const int gemm_grid = (N_NODES + TILE_M - 1) / TILE_M;   // 782
    const int agg_grid  = (N_NODES * 32 + 255) / 256;

    gemm_tf32_kernel<<<gemm_grid, 256, GEMM_SMEM_BYTES>>>(x, W0, Gp);
    agg_kernel_t<false><<<agg_grid, 256>>>(b0, Hp, Wl, bl);
    gemm_tf32_kernel<<<gemm_grid, 256, GEMM_SMEM_BYTES>>>(Hp, W1, Gp);
    agg_kernel_t<false><<<agg_grid, 256>>>(b1, Hp, Wl, bl);
    gemm_tf32_kernel<<<gemm_grid, 256, GEMM_SMEM_BYTES>>>(Hp, W2, Gp);
    agg_kernel_t<true><<<agg_grid, 256>>>(b2, Hp, Wl, bl);

    pool_kernel<<<N_GRAPHS, 256>>>(out);
}

// round 6
// speedup vs baseline: 1.7324x; 1.0722x over previous
#include <cuda_runtime.h>
#include <cuda_fp16.h>
#include <math.h>
#include <stdint.h>
#include <cstdint>

// Problem constants
#define N_NODES 50000
#define N_EDGES 800000
#define CH 128
#define OUT_CH 6
#define N_GRAPHS 64
#define MAX_DEG 96

// GEMM tile: M=64, N=128, K=128 (full K resident)
#define TILE_M 64
#define PKST 136   // packed row stride in words (136 % 32 == 8 -> conflict-free frags)
#define GEMM_SMEM_BYTES ((TILE_M * PKST + 128 * PKST) * 4)

// fragment-pack permutation: pairs (k, k+4) adjacent -> float2 loads
__host__ __device__ __forceinline__ int fperm(int k) {
    return ((k >> 3) << 3) + ((k & 3) << 1) + ((k >> 2) & 1);
}

// ---------------- static device scratch ----------------
__device__ int   g_is64;
__device__ int   g_batch[N_NODES];
__device__ int   g_cursor[N_NODES];
__device__ float g_dinv[N_NODES];
__device__ int   g_bucket[(size_t)N_NODES * MAX_DEG];
__device__ __half2 g_G16[(size_t)N_NODES * (CH / 2)];  // dv_j * (A@W)_j, fp16
__device__ float g_H[(size_t)N_NODES * CH];
__device__ float g_H6[(size_t)N_NODES * OUT_CH];
__device__ float g_Wpk0[128 * PKST];   // packed tf32 W per layer
__device__ float g_Wpk1[128 * PKST];
__device__ float g_Wpk2[128 * PKST];

// ---------------- zero cursors + dtype detect ----------------
__global__ void zero_detect_kernel(const unsigned int* __restrict__ ei_words) {
    int i = blockIdx.x * blockDim.x + threadIdx.x;
    if (i < N_NODES) g_cursor[i] = 0;
    if (blockIdx.x == 0) {
        __shared__ int nonzero;
        if (threadIdx.x == 0) nonzero = 0;
        __syncthreads();
        if (threadIdx.x < 128) {
            int idx = 2 * threadIdx.x + 1;
            if (ei_words[idx] != 0u) atomicOr(&nonzero, 1);
        }
        __syncthreads();
        if (threadIdx.x == 0) g_is64 = nonzero ? 0 : 1;
    }
}

__device__ __forceinline__ int read_idx(const void* p, long long i, int is64) {
    if (is64) return (int)((const long long*)p)[i];
    return ((const int*)p)[i];
}

__global__ void convfill_kernel(const void* __restrict__ edge_index,
                                const void* __restrict__ batch) {
    int is64 = g_is64;
    for (int e = blockIdx.x * blockDim.x + threadIdx.x; e < N_EDGES;
         e += gridDim.x * blockDim.x) {
        int s = read_idx(edge_index, e, is64);
        int d = read_idx(edge_index, (long long)N_EDGES + e, is64);
        int pos = atomicAdd(&g_cursor[d], 1);
        if (pos < MAX_DEG) g_bucket[(size_t)d * MAX_DEG + pos] = s;
    }
    for (int i = blockIdx.x * blockDim.x + threadIdx.x; i < N_NODES;
         i += gridDim.x * blockDim.x) {
        g_batch[i] = read_idx(batch, i, is64);
    }
}

__global__ void dinv_kernel() {
    for (int i = blockIdx.x * blockDim.x + threadIdx.x; i < N_NODES;
         i += gridDim.x * blockDim.x) {
        g_dinv[i] = rsqrtf((float)g_cursor[i] + 1.0f);
    }
}

// ---------------- W pre-pack: Wpk[n][fperm(k)] = tf32(W[k][n]) ----------------
__device__ __forceinline__ uint32_t f2tf32(float f) {
    uint32_t u;
    asm("cvt.rna.tf32.f32 %0, %1;" : "=r"(u) : "f"(f));
    return u;
}

__global__ void packW_kernel(const float* __restrict__ W, float* __restrict__ Wpk) {
    int t = blockIdx.x * blockDim.x + threadIdx.x;   // 16384 threads
    int nc = t >> 7;
    int k  = t & 127;
    Wpk[nc * PKST + fperm(k)] = __uint_as_float(f2tf32(W[(size_t)k * CH + nc]));
}

// ---------------- tf32 TC GEMM: G16 = fp16(dinv .* (A @ W)) ----------------
__global__ __launch_bounds__(256)
void gemm_tf32_kernel(const float* __restrict__ A, const float* __restrict__ Wpk) {
    extern __shared__ float smem[];
    float* As = smem;                     // [m:64][fperm(k) : PKST]
    float* Ws = smem + TILE_M * PKST;     // [n:128][fperm(k) : PKST]

    const int tid = threadIdx.x;
    const int block_row = blockIdx.x * TILE_M;

    // Stage A: scalar loads (coalesced), conflict-free packed stores
#pragma unroll
    for (int it = 0; it < 32; it++) {
        int u = tid + it * 256;           // 8192 scalars (64 x 128)
        int m = u >> 7;
        int k = u & 127;
        int gm = block_row + m;
        if (gm >= N_NODES) gm = N_NODES - 1;
        float v = __ldg(A + (size_t)gm * CH + k);
        As[m * PKST + fperm(k)] = __uint_as_float(f2tf32(v));
    }
    // Stage W: straight copy of pre-packed tile
#pragma unroll
    for (int it = 0; it < 17; it++) {
        int u = tid + it * 256;           // 4352 float4s
        *(float4*)&Ws[u * 4] = __ldg((const float4*)(Wpk + u * 4));
    }
    __syncthreads();

    const int lane = tid & 31;
    const int warp = tid >> 5;
    const int wm = (warp & 1) * 32;       // 2 warps along M
    const int wn = (warp >> 1) * 32;      // 4 warps along N

    const int lq = lane >> 2;             // 0..7
    const int lr = lane & 3;              // 0..3

    float c[2][4][4];
#pragma unroll
    for (int mt = 0; mt < 2; mt++)
#pragma unroll
        for (int nt = 0; nt < 4; nt++)
#pragma unroll
            for (int q = 0; q < 4; q++) c[mt][nt][q] = 0.0f;

    const int abase = (wm + lq) * PKST + 2 * lr;
    const int bbase = (wn + lq) * PKST + 2 * lr;

#pragma unroll
    for (int ks = 0; ks < 16; ks++) {
        const int k8 = ks * 8;
        uint32_t a[2][4];
#pragma unroll
        for (int mt = 0; mt < 2; mt++) {
            float2 lo0 = *(const float2*)&As[abase + mt * (16 * PKST) + k8];
            float2 lo1 = *(const float2*)&As[abase + mt * (16 * PKST) + 8 * PKST + k8];
            a[mt][0] = __float_as_uint(lo0.x);
            a[mt][1] = __float_as_uint(lo1.x);
            a[mt][2] = __float_as_uint(lo0.y);
            a[mt][3] = __float_as_uint(lo1.y);
        }
#pragma unroll
        for (int nt = 0; nt < 4; nt++) {
            float2 bv = *(const float2*)&Ws[bbase + nt * (8 * PKST) + k8];
            uint32_t b0 = __float_as_uint(bv.x);
            uint32_t b1 = __float_as_uint(bv.y);
#pragma unroll
            for (int mt = 0; mt < 2; mt++) {
                asm volatile(
                    "mma.sync.aligned.m16n8k8.row.col.f32.tf32.tf32.f32 "
                    "{%0,%1,%2,%3}, {%4,%5,%6,%7}, {%8,%9}, {%0,%1,%2,%3};"
                    : "+f"(c[mt][nt][0]), "+f"(c[mt][nt][1]),
                      "+f"(c[mt][nt][2]), "+f"(c[mt][nt][3])
                    : "r"(a[mt][0]), "r"(a[mt][1]), "r"(a[mt][2]), "r"(a[mt][3]),
                      "r"(b0), "r"(b1));
            }
        }
    }

    // Epilogue: scale by dinv, pack to fp16 pairs
#pragma unroll
    for (int mt = 0; mt < 2; mt++) {
        int r0 = block_row + wm + mt * 16 + lq;
        int r1 = r0 + 8;
        if (r0 < N_NODES) {
            float s = g_dinv[r0];
#pragma unroll
            for (int nt = 0; nt < 4; nt++) {
                __half2 p = __floats2half2_rn(c[mt][nt][0] * s, c[mt][nt][1] * s);
                g_G16[(size_t)r0 * (CH / 2) + (wn >> 1) + nt * 4 + lr] = p;
            }
        }
        if (r1 < N_NODES) {
            float s = g_dinv[r1];
#pragma unroll
            for (int nt = 0; nt < 4; nt++) {
                __half2 p = __floats2half2_rn(c[mt][nt][2] * s, c[mt][nt][3] * s);
                g_G16[(size_t)r1 * (CH / 2) + (wn >> 1) + nt * 4 + lr] = p;
            }
        }
    }
}

// ---------------- Aggregation: H[i] = tanh(dv_i*(g16_i + sum_j g16_j) + b) ----------------
// stored g16_k = dv_k * G_k. One warp per node, lane handles 4 channels (uint2 = 2 half2).
template <bool LAST>
__global__ __launch_bounds__(256)
void agg_kernel_t(const float* __restrict__ b, float* __restrict__ H,
                  const float* __restrict__ Wl, const float* __restrict__ bl) {
    const int lane = threadIdx.x & 31;
    const int warp = (blockIdx.x * blockDim.x + threadIdx.x) >> 5;
    if (warp >= N_NODES) return;
    const int i = warp;

    const __half2* Grow = g_G16 + (size_t)i * (CH / 2) + lane * 2;
    float2 f0 = __half22float2(__ldg(Grow));
    float2 f1 = __half22float2(__ldg(Grow + 1));
    float4 acc = make_float4(f0.x, f0.y, f1.x, f1.y);

    int deg = g_cursor[i];
    if (deg > MAX_DEG) deg = MAX_DEG;
    const int* bk = g_bucket + (size_t)i * MAX_DEG;

    int j = 0;
    for (; j + 4 <= deg; j += 4) {
        int s0 = __ldg(bk + j);
        int s1 = __ldg(bk + j + 1);
        int s2 = __ldg(bk + j + 2);
        int s3 = __ldg(bk + j + 3);
        uint2 v0 = __ldg((const uint2*)(g_G16 + (size_t)s0 * (CH / 2) + lane * 2));
        uint2 v1 = __ldg((const uint2*)(g_G16 + (size_t)s1 * (CH / 2) + lane * 2));
        uint2 v2 = __ldg((const uint2*)(g_G16 + (size_t)s2 * (CH / 2) + lane * 2));
        uint2 v3 = __ldg((const uint2*)(g_G16 + (size_t)s3 * (CH / 2) + lane * 2));
#pragma unroll
        for (int q = 0; q < 4; q++) {
            uint2 v = (q == 0) ? v0 : (q == 1) ? v1 : (q == 2) ? v2 : v3;
            float2 a0 = __half22float2(*(__half2*)&v.x);
            float2 a1 = __half22float2(*(__half2*)&v.y);
            acc.x += a0.x; acc.y += a0.y; acc.z += a1.x; acc.w += a1.y;
        }
    }
    for (; j < deg; j++) {
        int s = __ldg(bk + j);
        uint2 v = __ldg((const uint2*)(g_G16 + (size_t)s * (CH / 2) + lane * 2));
        float2 a0 = __half22float2(*(__half2*)&v.x);
        float2 a1 = __half22float2(*(__half2*)&v.y);
        acc.x += a0.x; acc.y += a0.y; acc.z += a1.x; acc.w += a1.y;
    }

    float dv = g_dinv[i];
    float4 bb = *(const float4*)(b + lane * 4);
    float4 o;
    o.x = tanhf(fmaf(dv, acc.x, bb.x));
    o.y = tanhf(fmaf(dv, acc.y, bb.y));
    o.z = tanhf(fmaf(dv, acc.z, bb.z));
    o.w = tanhf(fmaf(dv, acc.w, bb.w));

    if (!LAST) {
        *(float4*)(H + (size_t)i * CH + lane * 4) = o;
    } else {
        int k = lane * 4;
#pragma unroll
        for (int cidx = 0; cidx < OUT_CH; cidx++) {
            float p = o.x * Wl[(k + 0) * OUT_CH + cidx]
                    + o.y * Wl[(k + 1) * OUT_CH + cidx]
                    + o.z * Wl[(k + 2) * OUT_CH + cidx]
                    + o.w * Wl[(k + 3) * OUT_CH + cidx];
#pragma unroll
            for (int off = 16; off > 0; off >>= 1)
                p += __shfl_xor_sync(0xffffffffu, p, off);
            if (lane == 0) g_H6[(size_t)i * OUT_CH + cidx] = tanhf(p + bl[cidx]);
        }
    }
}

// ---------------- Pool ----------------
__global__ __launch_bounds__(256)
void pool_kernel(float* __restrict__ out) {
    const int g = blockIdx.x;
    __shared__ int s_lo, s_hi;
    __shared__ float ssum[OUT_CH];
    if (threadIdx.x == 0) {
        int lo = 0, hi = N_NODES;
        while (lo < hi) { int m = (lo + hi) >> 1; if (g_batch[m] < g) lo = m + 1; else hi = m; }
        s_lo = lo;
        int lo2 = lo, hi2 = N_NODES;
        while (lo2 < hi2) { int m = (lo2 + hi2) >> 1; if (g_batch[m] < g + 1) lo2 = m + 1; else hi2 = m; }
        s_hi = lo2;
    }
    if (threadIdx.x < OUT_CH) ssum[threadIdx.x] = 0.0f;
    __syncthreads();
    int lo = s_lo, hi = s_hi;
    float loc[OUT_CH];
#pragma unroll
    for (int c = 0; c < OUT_CH; c++) loc[c] = 0.0f;
    for (int i = lo + threadIdx.x; i < hi; i += blockDim.x) {
#pragma unroll
        for (int c = 0; c < OUT_CH; c++) loc[c] += g_H6[(size_t)i * OUT_CH + c];
    }
#pragma unroll
    for (int c = 0; c < OUT_CH; c++) {
#pragma unroll
        for (int off = 16; off > 0; off >>= 1)
            loc[c] += __shfl_xor_sync(0xffffffffu, loc[c], off);
    }
    if ((threadIdx.x & 31) == 0) {
#pragma unroll
        for (int c = 0; c < OUT_CH; c++) atomicAdd(&ssum[c], loc[c]);
    }
    __syncthreads();
    if (threadIdx.x < OUT_CH) {
        float cnt = (float)(hi - lo);
        if (cnt < 1.0f) cnt = 1.0f;
        out[g * OUT_CH + threadIdx.x] = ssum[threadIdx.x] / cnt;
    }
}

// ---------------- launch ----------------
extern "C" void kernel_launch(void* const* d_in, const int* in_sizes, int n_in,
                              void* d_out, int out_size) {
    const float* x   = (const float*)d_in[0];
    const void*  ei  = d_in[1];
    const void*  bat = d_in[2];
    const float* W0  = (const float*)d_in[3];
    const float* b0  = (const float*)d_in[4];
    const float* W1  = (const float*)d_in[5];
    const float* b1  = (const float*)d_in[6];
    const float* W2  = (const float*)d_in[7];
    const float* b2  = (const float*)d_in[8];
    const float* Wl  = (const float*)d_in[9];
    const float* bl  = (const float*)d_in[10];
    float* out = (float*)d_out;

    float *Hp, *Wpk0, *Wpk1, *Wpk2;
    cudaGetSymbolAddress((void**)&Hp, g_H);
    cudaGetSymbolAddress((void**)&Wpk0, g_Wpk0);
    cudaGetSymbolAddress((void**)&Wpk1, g_Wpk1);
    cudaGetSymbolAddress((void**)&Wpk2, g_Wpk2);

    cudaFuncSetAttribute(gemm_tf32_kernel,
                         cudaFuncAttributeMaxDynamicSharedMemorySize,
                         GEMM_SMEM_BYTES);

    zero_detect_kernel<<<(N_NODES + 255) / 256, 256>>>((const unsigned int*)ei);
    packW_kernel<<<64, 256>>>(W0, Wpk0);
    packW_kernel<<<64, 256>>>(W1, Wpk1);
    packW_kernel<<<64, 256>>>(W2, Wpk2);
    convfill_kernel<<<(N_EDGES + 255) / 256, 256>>>(ei, bat);
    dinv_kernel<<<(N_NODES + 255) / 256, 256>>>();

    const int gemm_grid = (N_NODES + TILE_M - 1) / TILE_M;   // 782
    const int agg_grid  = (N_NODES * 32 + 255) / 256;

    gemm_tf32_kernel<<<gemm_grid, 256, GEMM_SMEM_BYTES>>>(x, Wpk0);
    agg_kernel_t<false><<<agg_grid, 256>>>(b0, Hp, Wl, bl);
    gemm_tf32_kernel<<<gemm_grid, 256, GEMM_SMEM_BYTES>>>(Hp, Wpk1);
    agg_kernel_t<false><<<agg_grid, 256>>>(b1, Hp, Wl, bl);
    gemm_tf32_kernel<<<gemm_grid, 256, GEMM_SMEM_BYTES>>>(Hp, Wpk2);
    agg_kernel_t<true><<<agg_grid, 256>>>(b2, Hp, Wl, bl);

    pool_kernel<<<N_GRAPHS, 256>>>(out);
}

// round 7
// speedup vs baseline: 1.8033x; 1.0409x over previous
#include <cuda_runtime.h>
#include <cuda_fp16.h>
#include <math.h>
#include <stdint.h>
#include <cstdint>

// Problem constants
#define N_NODES 50000
#define N_EDGES 800000
#define CH 128
#define OUT_CH 6
#define N_GRAPHS 64
#define MAX_DEG 96

// GEMM tile: M=64, N=128, K=128 (full K resident)
#define TILE_M 64
#define PKST 136   // packed row stride in words (136 % 32 == 8 -> conflict-free frags)
#define GEMM_SMEM_BYTES ((TILE_M * PKST + 128 * PKST) * 4)

// fragment-pack permutation: pairs (k, k+4) adjacent -> float2 loads
__host__ __device__ __forceinline__ int fperm(int k) {
    return ((k >> 3) << 3) + ((k & 3) << 1) + ((k >> 2) & 1);
}

// ---------------- static device scratch ----------------
__device__ int   g_is64;
__device__ int   g_batch[N_NODES];
__device__ int   g_cursor[N_NODES];
__device__ int   g_bucket[(size_t)N_NODES * MAX_DEG];   // 16B-aligned rows (384B)
__device__ __half2 g_G16[(size_t)N_NODES * (CH / 2)];   // dv_j * (A@W)_j, fp16
__device__ __half2 g_H16[(size_t)N_NODES * (CH / 2)];   // layer output, fp16
__device__ float g_H6[(size_t)N_NODES * OUT_CH];
__device__ float g_Wpk[3][128 * PKST];                  // packed tf32 W per layer

// ---------------- zero cursors + dtype detect ----------------
__global__ void zero_detect_kernel(const unsigned int* __restrict__ ei_words) {
    int i = blockIdx.x * blockDim.x + threadIdx.x;
    if (i < N_NODES) g_cursor[i] = 0;
    if (blockIdx.x == 0) {
        __shared__ int nonzero;
        if (threadIdx.x == 0) nonzero = 0;
        __syncthreads();
        if (threadIdx.x < 128) {
            int idx = 2 * threadIdx.x + 1;
            if (ei_words[idx] != 0u) atomicOr(&nonzero, 1);
        }
        __syncthreads();
        if (threadIdx.x == 0) g_is64 = nonzero ? 0 : 1;
    }
}

__device__ __forceinline__ int read_idx(const void* p, long long i, int is64) {
    if (is64) return (int)((const long long*)p)[i];
    return ((const int*)p)[i];
}

__global__ void convfill_kernel(const void* __restrict__ edge_index,
                                const void* __restrict__ batch) {
    int is64 = g_is64;
    for (int e = blockIdx.x * blockDim.x + threadIdx.x; e < N_EDGES;
         e += gridDim.x * blockDim.x) {
        int s = read_idx(edge_index, e, is64);
        int d = read_idx(edge_index, (long long)N_EDGES + e, is64);
        int pos = atomicAdd(&g_cursor[d], 1);
        if (pos < MAX_DEG) g_bucket[(size_t)d * MAX_DEG + pos] = s;
    }
    for (int i = blockIdx.x * blockDim.x + threadIdx.x; i < N_NODES;
         i += gridDim.x * blockDim.x) {
        g_batch[i] = read_idx(batch, i, is64);
    }
}

// ---------------- W pre-pack (all 3 layers, one launch) ----------------
__device__ __forceinline__ uint32_t f2tf32(float f) {
    uint32_t u;
    asm("cvt.rna.tf32.f32 %0, %1;" : "=r"(u) : "f"(f));
    return u;
}

__global__ void packW_all_kernel(const float* __restrict__ W0,
                                 const float* __restrict__ W1,
                                 const float* __restrict__ W2) {
    int t = blockIdx.x * blockDim.x + threadIdx.x;   // 0..49151
    int layer = t >> 14;
    int u = t & 16383;
    int nc = u >> 7;
    int k  = u & 127;
    const float* W = (layer == 0) ? W0 : (layer == 1) ? W1 : W2;
    g_Wpk[layer][nc * PKST + fperm(k)] = __uint_as_float(f2tf32(W[(size_t)k * CH + nc]));
}

// ---------------- tf32 TC GEMM: G16 = fp16(dinv .* (A @ W)) ----------------
// FP16A=false: A is fp32 [N_NODES,128]; FP16A=true: A is g_H16 (fp16)
template <bool FP16A>
__global__ __launch_bounds__(256)
void gemm_tf32_kernel(const float* __restrict__ A32, const float* __restrict__ Wpk) {
    extern __shared__ float smem[];
    float* As = smem;                     // [m:64][fperm(k) : PKST]
    float* Ws = smem + TILE_M * PKST;     // [n:128][fperm(k) : PKST]

    const int tid = threadIdx.x;
    const int block_row = blockIdx.x * TILE_M;

    if (!FP16A) {
        // Stage A fp32: scalar loads (coalesced), conflict-free packed stores
#pragma unroll
        for (int it = 0; it < 32; it++) {
            int u = tid + it * 256;       // 8192 scalars (64 x 128)
            int m = u >> 7;
            int k = u & 127;
            int gm = block_row + m;
            if (gm >= N_NODES) gm = N_NODES - 1;
            float v = __ldg(A32 + (size_t)gm * CH + k);
            As[m * PKST + fperm(k)] = __uint_as_float(f2tf32(v));
        }
    } else {
        // Stage A fp16: half2 loads, two packed stores each
#pragma unroll
        for (int it = 0; it < 16; it++) {
            int u = tid + it * 256;       // 4096 half2s (64 x 64)
            int m = u >> 6;
            int h = u & 63;
            int gm = block_row + m;
            if (gm >= N_NODES) gm = N_NODES - 1;
            __half2 hv = __ldg(g_H16 + (size_t)gm * (CH / 2) + h);
            float2 f = __half22float2(hv);
            int k = h * 2;
            As[m * PKST + fperm(k)]     = __uint_as_float(f2tf32(f.x));
            As[m * PKST + fperm(k + 1)] = __uint_as_float(f2tf32(f.y));
        }
    }
    // Stage W: straight copy of pre-packed tile
#pragma unroll
    for (int it = 0; it < 17; it++) {
        int u = tid + it * 256;           // 4352 float4s
        *(float4*)&Ws[u * 4] = __ldg((const float4*)(Wpk + u * 4));
    }
    __syncthreads();

    const int lane = tid & 31;
    const int warp = tid >> 5;
    const int wm = (warp & 1) * 32;       // 2 warps along M
    const int wn = (warp >> 1) * 32;      // 4 warps along N

    const int lq = lane >> 2;             // 0..7
    const int lr = lane & 3;              // 0..3

    float c[2][4][4];
#pragma unroll
    for (int mt = 0; mt < 2; mt++)
#pragma unroll
        for (int nt = 0; nt < 4; nt++)
#pragma unroll
            for (int q = 0; q < 4; q++) c[mt][nt][q] = 0.0f;

    const int abase = (wm + lq) * PKST + 2 * lr;
    const int bbase = (wn + lq) * PKST + 2 * lr;

#pragma unroll
    for (int ks = 0; ks < 16; ks++) {
        const int k8 = ks * 8;
        uint32_t a[2][4];
#pragma unroll
        for (int mt = 0; mt < 2; mt++) {
            float2 lo0 = *(const float2*)&As[abase + mt * (16 * PKST) + k8];
            float2 lo1 = *(const float2*)&As[abase + mt * (16 * PKST) + 8 * PKST + k8];
            a[mt][0] = __float_as_uint(lo0.x);
            a[mt][1] = __float_as_uint(lo1.x);
            a[mt][2] = __float_as_uint(lo0.y);
            a[mt][3] = __float_as_uint(lo1.y);
        }
#pragma unroll
        for (int nt = 0; nt < 4; nt++) {
            float2 bv = *(const float2*)&Ws[bbase + nt * (8 * PKST) + k8];
            uint32_t b0 = __float_as_uint(bv.x);
            uint32_t b1 = __float_as_uint(bv.y);
#pragma unroll
            for (int mt = 0; mt < 2; mt++) {
                asm volatile(
                    "mma.sync.aligned.m16n8k8.row.col.f32.tf32.tf32.f32 "
                    "{%0,%1,%2,%3}, {%4,%5,%6,%7}, {%8,%9}, {%0,%1,%2,%3};"
                    : "+f"(c[mt][nt][0]), "+f"(c[mt][nt][1]),
                      "+f"(c[mt][nt][2]), "+f"(c[mt][nt][3])
                    : "r"(a[mt][0]), "r"(a[mt][1]), "r"(a[mt][2]), "r"(a[mt][3]),
                      "r"(b0), "r"(b1));
            }
        }
    }

    // Epilogue: dv = rsqrt(deg+1) inline, pack to fp16 pairs
#pragma unroll
    for (int mt = 0; mt < 2; mt++) {
        int r0 = block_row + wm + mt * 16 + lq;
        int r1 = r0 + 8;
        if (r0 < N_NODES) {
            float s = rsqrtf((float)g_cursor[r0] + 1.0f);
#pragma unroll
            for (int nt = 0; nt < 4; nt++) {
                __half2 p = __floats2half2_rn(c[mt][nt][0] * s, c[mt][nt][1] * s);
                g_G16[(size_t)r0 * (CH / 2) + (wn >> 1) + nt * 4 + lr] = p;
            }
        }
        if (r1 < N_NODES) {
            float s = rsqrtf((float)g_cursor[r1] + 1.0f);
#pragma unroll
            for (int nt = 0; nt < 4; nt++) {
                __half2 p = __floats2half2_rn(c[mt][nt][2] * s, c[mt][nt][3] * s);
                g_G16[(size_t)r1 * (CH / 2) + (wn >> 1) + nt * 4 + lr] = p;
            }
        }
    }
}

// ---------------- Aggregation ----------------
// H[i] = tanh(dv_i*(g16_i + sum_j g16_j) + b),  g16_k = dv_k*G_k
// One warp per node; vector index prefetch (int4 x2) + 8 predicated gathers.
template <bool LAST>
__global__ __launch_bounds__(256)
void agg_kernel_t(const float* __restrict__ b,
                  const float* __restrict__ Wl, const float* __restrict__ bl) {
    const int lane = threadIdx.x & 31;
    const int warp = (blockIdx.x * blockDim.x + threadIdx.x) >> 5;
    if (warp >= N_NODES) return;
    const int i = warp;

    const int cur = g_cursor[i];
    const float dv = rsqrtf((float)cur + 1.0f);
    int deg = cur > MAX_DEG ? MAX_DEG : cur;

    const uint2* Gb = (const uint2*)g_G16;
    uint2 sv = __ldg(Gb + (size_t)i * 32 + lane);   // 32 uint2 per row
    float2 f0 = __half22float2(*(__half2*)&sv.x);
    float2 f1 = __half22float2(*(__half2*)&sv.y);
    float4 acc = make_float4(f0.x, f0.y, f1.x, f1.y);

    const int* bk = g_bucket + (size_t)i * MAX_DEG;

    for (int j = 0; j < deg; j += 8) {
        int4 ia = *(const int4*)(bk + j);         // in-row over-read safe (row=96)
        int4 ib = *(const int4*)(bk + j + 4);
        int s[8] = {ia.x, ia.y, ia.z, ia.w, ib.x, ib.y, ib.z, ib.w};
        uint2 v[8];
#pragma unroll
        for (int q = 0; q < 8; q++) {
            v[q] = (j + q < deg) ? __ldg(Gb + (size_t)s[q] * 32 + lane)
                                 : make_uint2(0u, 0u);   // half2 zeros
        }
#pragma unroll
        for (int q = 0; q < 8; q++) {
            float2 a0 = __half22float2(*(__half2*)&v[q].x);
            float2 a1 = __half22float2(*(__half2*)&v[q].y);
            acc.x += a0.x; acc.y += a0.y; acc.z += a1.x; acc.w += a1.y;
        }
    }

    float4 bb = *(const float4*)(b + lane * 4);
    float4 o;
    o.x = tanhf(fmaf(dv, acc.x, bb.x));
    o.y = tanhf(fmaf(dv, acc.y, bb.y));
    o.z = tanhf(fmaf(dv, acc.z, bb.z));
    o.w = tanhf(fmaf(dv, acc.w, bb.w));

    if (!LAST) {
        uint2 st;
        *(__half2*)&st.x = __floats2half2_rn(o.x, o.y);
        *(__half2*)&st.y = __floats2half2_rn(o.z, o.w);
        *((uint2*)g_H16 + (size_t)i * 32 + lane) = st;
    } else {
        int k = lane * 4;
#pragma unroll
        for (int cidx = 0; cidx < OUT_CH; cidx++) {
            float p = o.x * Wl[(k + 0) * OUT_CH + cidx]
                    + o.y * Wl[(k + 1) * OUT_CH + cidx]
                    + o.z * Wl[(k + 2) * OUT_CH + cidx]
                    + o.w * Wl[(k + 3) * OUT_CH + cidx];
#pragma unroll
            for (int off = 16; off > 0; off >>= 1)
                p += __shfl_xor_sync(0xffffffffu, p, off);
            if (lane == 0) g_H6[(size_t)i * OUT_CH + cidx] = tanhf(p + bl[cidx]);
        }
    }
}

// ---------------- Pool ----------------
__global__ __launch_bounds__(256)
void pool_kernel(float* __restrict__ out) {
    const int g = blockIdx.x;
    __shared__ int s_lo, s_hi;
    __shared__ float ssum[OUT_CH];
    if (threadIdx.x == 0) {
        int lo = 0, hi = N_NODES;
        while (lo < hi) { int m = (lo + hi) >> 1; if (g_batch[m] < g) lo = m + 1; else hi = m; }
        s_lo = lo;
        int lo2 = lo, hi2 = N_NODES;
        while (lo2 < hi2) { int m = (lo2 + hi2) >> 1; if (g_batch[m] < g + 1) lo2 = m + 1; else hi2 = m; }
        s_hi = lo2;
    }
    if (threadIdx.x < OUT_CH) ssum[threadIdx.x] = 0.0f;
    __syncthreads();
    int lo = s_lo, hi = s_hi;
    float loc[OUT_CH];
#pragma unroll
    for (int c = 0; c < OUT_CH; c++) loc[c] = 0.0f;
    for (int i = lo + threadIdx.x; i < hi; i += blockDim.x) {
#pragma unroll
        for (int c = 0; c < OUT_CH; c++) loc[c] += g_H6[(size_t)i * OUT_CH + c];
    }
#pragma unroll
    for (int c = 0; c < OUT_CH; c++) {
#pragma unroll
        for (int off = 16; off > 0; off >>= 1)
            loc[c] += __shfl_xor_sync(0xffffffffu, loc[c], off);
    }
    if ((threadIdx.x & 31) == 0) {
#pragma unroll
        for (int c = 0; c < OUT_CH; c++) atomicAdd(&ssum[c], loc[c]);
    }
    __syncthreads();
    if (threadIdx.x < OUT_CH) {
        float cnt = (float)(hi - lo);
        if (cnt < 1.0f) cnt = 1.0f;
        out[g * OUT_CH + threadIdx.x] = ssum[threadIdx.x] / cnt;
    }
}

// ---------------- launch ----------------
extern "C" void kernel_launch(void* const* d_in, const int* in_sizes, int n_in,
                              void* d_out, int out_size) {
    const float* x   = (const float*)d_in[0];
    const void*  ei  = d_in[1];
    const void*  bat = d_in[2];
    const float* W0  = (const float*)d_in[3];
    const float* b0  = (const float*)d_in[4];
    const float* W1  = (const float*)d_in[5];
    const float* b1  = (const float*)d_in[6];
    const float* W2  = (const float*)d_in[7];
    const float* b2  = (const float*)d_in[8];
    const float* Wl  = (const float*)d_in[9];
    const float* bl  = (const float*)d_in[10];
    float* out = (float*)d_out;

    float* Wpk;
    cudaGetSymbolAddress((void**)&Wpk, g_Wpk);

    cudaFuncSetAttribute(gemm_tf32_kernel<false>,
                         cudaFuncAttributeMaxDynamicSharedMemorySize,
                         GEMM_SMEM_BYTES);
    cudaFuncSetAttribute(gemm_tf32_kernel<true>,
                         cudaFuncAttributeMaxDynamicSharedMemorySize,
                         GEMM_SMEM_BYTES);

    zero_detect_kernel<<<(N_NODES + 255) / 256, 256>>>((const unsigned int*)ei);
    packW_all_kernel<<<192, 256>>>(W0, W1, W2);
    convfill_kernel<<<(N_EDGES + 255) / 256, 256>>>(ei, bat);

    const int gemm_grid = (N_NODES + TILE_M - 1) / TILE_M;   // 782
    const int agg_grid  = (N_NODES * 32 + 255) / 256;

    gemm_tf32_kernel<false><<<gemm_grid, 256, GEMM_SMEM_BYTES>>>(x, Wpk);
    agg_kernel_t<false><<<agg_grid, 256>>>(b0, Wl, bl);
    gemm_tf32_kernel<true><<<gemm_grid, 256, GEMM_SMEM_BYTES>>>(nullptr, Wpk + 128 * PKST);
    agg_kernel_t<false><<<agg_grid, 256>>>(b1, Wl, bl);
    gemm_tf32_kernel<true><<<gemm_grid, 256, GEMM_SMEM_BYTES>>>(nullptr, Wpk + 2 * 128 * PKST);
    agg_kernel_t<true><<<agg_grid, 256>>>(b2, Wl, bl);

    pool_kernel<<<N_GRAPHS, 256>>>(out);
}

// round 8
// speedup vs baseline: 2.1060x; 1.1679x over previous
#include <cuda_runtime.h>
#include <cuda_fp16.h>
#include <math.h>
#include <stdint.h>
#include <cstdint>

// Problem constants
#define N_NODES 50000
#define N_EDGES 800000
#define CH 128
#define OUT_CH 6
#define N_GRAPHS 64
#define MAX_DEG 96

// GEMM tile: M=64, N=128, K=128 (full K resident), fp16 operands in smem
#define TILE_M 64
#define SMEM_A_BYTES (TILE_M * 256)          // 64 rows x 128 fp16
#define SMEM_W_BYTES (128 * 256)             // 128 rows x 128 fp16
#define GEMM_SMEM_BYTES (SMEM_A_BYTES + SMEM_W_BYTES)   // 48 KB

// ---------------- static device scratch ----------------
__device__ int   g_is64;
__device__ int   g_batch[N_NODES];
__device__ int   g_cursor[N_NODES];
__device__ int   g_bucket[(size_t)N_NODES * MAX_DEG];   // 16B-aligned rows (384B)
__device__ __half2 g_G16[(size_t)N_NODES * (CH / 2)];   // dv_j * (A@W)_j, fp16
__device__ __half2 g_H16[(size_t)N_NODES * (CH / 2)];   // layer output, fp16
__device__ float g_H6[(size_t)N_NODES * OUT_CH];
__device__ __half g_Wpk16[3][128 * 128];                // fp16 W, pre-swizzled

// ---------------- zero cursors + dtype detect ----------------
__global__ void zero_detect_kernel(const unsigned int* __restrict__ ei_words) {
    int i = blockIdx.x * blockDim.x + threadIdx.x;
    if (i < N_NODES) g_cursor[i] = 0;
    if (blockIdx.x == 0) {
        __shared__ int nonzero;
        if (threadIdx.x == 0) nonzero = 0;
        __syncthreads();
        if (threadIdx.x < 128) {
            int idx = 2 * threadIdx.x + 1;
            if (ei_words[idx] != 0u) atomicOr(&nonzero, 1);
        }
        __syncthreads();
        if (threadIdx.x == 0) g_is64 = nonzero ? 0 : 1;
    }
}

__device__ __forceinline__ int read_idx(const void* p, long long i, int is64) {
    if (is64) return (int)((const long long*)p)[i];
    return ((const int*)p)[i];
}

__global__ void convfill_kernel(const void* __restrict__ edge_index,
                                const void* __restrict__ batch) {
    int is64 = g_is64;
    for (int e = blockIdx.x * blockDim.x + threadIdx.x; e < N_EDGES;
         e += gridDim.x * blockDim.x) {
        int s = read_idx(edge_index, e, is64);
        int d = read_idx(edge_index, (long long)N_EDGES + e, is64);
        int pos = atomicAdd(&g_cursor[d], 1);
        if (pos < MAX_DEG) g_bucket[(size_t)d * MAX_DEG + pos] = s;
    }
    for (int i = blockIdx.x * blockDim.x + threadIdx.x; i < N_NODES;
         i += gridDim.x * blockDim.x) {
        g_batch[i] = read_idx(batch, i, is64);
    }
}

// ---------------- W pre-pack: fp16 + XOR swizzle, all 3 layers ----------------
// layout: row k (256B = 16 chunks of 16B); element n goes to chunk (n/8)^(k&7), slot n%8
__global__ void packW_all_kernel(const float* __restrict__ W0,
                                 const float* __restrict__ W1,
                                 const float* __restrict__ W2) {
    int t = blockIdx.x * blockDim.x + threadIdx.x;   // 0..49151
    int layer = t >> 14;
    int u = t & 16383;
    int k = u >> 7;
    int n = u & 127;
    const float* W = (layer == 0) ? W0 : (layer == 1) ? W1 : W2;
    int c = (n >> 3) ^ (k & 7);
    g_Wpk16[layer][k * 128 + (c << 3) + (n & 7)] = __float2half(W[(size_t)k * CH + n]);
}

// ---------------- ldmatrix wrappers ----------------
__device__ __forceinline__ void ldsm_x4(uint32_t& r0, uint32_t& r1,
                                        uint32_t& r2, uint32_t& r3, uint32_t addr) {
    asm volatile("ldmatrix.sync.aligned.m8n8.x4.shared.b16 {%0,%1,%2,%3}, [%4];"
                 : "=r"(r0), "=r"(r1), "=r"(r2), "=r"(r3) : "r"(addr));
}
__device__ __forceinline__ void ldsm_x4_t(uint32_t& r0, uint32_t& r1,
                                          uint32_t& r2, uint32_t& r3, uint32_t addr) {
    asm volatile("ldmatrix.sync.aligned.m8n8.x4.trans.shared.b16 {%0,%1,%2,%3}, [%4];"
                 : "=r"(r0), "=r"(r1), "=r"(r2), "=r"(r3) : "r"(addr));
}

// ---------------- fp16 TC GEMM: G16 = fp16(dinv .* (A @ W)) ----------------
// FP16A=false: A is fp32 [N_NODES,128]; FP16A=true: A is g_H16 (fp16)
template <bool FP16A>
__global__ __launch_bounds__(256)
void gemm_fp16_kernel(const float* __restrict__ A32, const __half* __restrict__ Wpk) {
    extern __shared__ char smem[];
    char* smA = smem;                       // [m:64][256B swizzled]
    char* smW = smem + SMEM_A_BYTES;        // [k:128][256B swizzled]

    const int tid = threadIdx.x;
    const int block_row = blockIdx.x * TILE_M;

    // ---- Stage A: 1024 16B chunks ----
    if (!FP16A) {
#pragma unroll
        for (int it = 0; it < 4; it++) {
            int u = tid + it * 256;
            int m = u >> 4;
            int c = u & 15;
            int gm = block_row + m;
            if (gm >= N_NODES) gm = N_NODES - 1;
            float4 v0 = __ldg((const float4*)(A32 + (size_t)gm * CH + c * 8));
            float4 v1 = __ldg((const float4*)(A32 + (size_t)gm * CH + c * 8 + 4));
            uint4 st;
            *(__half2*)&st.x = __floats2half2_rn(v0.x, v0.y);
            *(__half2*)&st.y = __floats2half2_rn(v0.z, v0.w);
            *(__half2*)&st.z = __floats2half2_rn(v1.x, v1.y);
            *(__half2*)&st.w = __floats2half2_rn(v1.z, v1.w);
            *(uint4*)(smA + m * 256 + ((c ^ (m & 7)) << 4)) = st;
        }
    } else {
#pragma unroll
        for (int it = 0; it < 4; it++) {
            int u = tid + it * 256;
            int m = u >> 4;
            int c = u & 15;
            int gm = block_row + m;
            if (gm >= N_NODES) gm = N_NODES - 1;
            uint4 v = __ldg((const uint4*)g_H16 + (size_t)gm * 16 + c);
            *(uint4*)(smA + m * 256 + ((c ^ (m & 7)) << 4)) = v;
        }
    }
    // ---- Stage W: straight copy of pre-swizzled tile (2048 16B chunks) ----
#pragma unroll
    for (int it = 0; it < 8; it++) {
        int u = tid + it * 256;
        ((uint4*)smW)[u] = __ldg((const uint4*)Wpk + u);
    }
    __syncthreads();

    const int lane = tid & 31;
    const int warp = tid >> 5;
    const int wm = (warp & 1) * 32;       // 2 warps along M
    const int wn = (warp >> 1) * 32;      // 4 warps along N

    const int lq = lane >> 2;             // 0..7
    const int lr = lane & 3;              // 0..3
    const int l7 = lane & 7;
    const int l8 = (lane >> 3) & 1;
    const int l16 = lane >> 4;            // 0..1

    uint32_t smA_u = (uint32_t)__cvta_generic_to_shared(smA);
    uint32_t smW_u = (uint32_t)__cvta_generic_to_shared(smW);

    float c[2][4][4];
#pragma unroll
    for (int mt = 0; mt < 2; mt++)
#pragma unroll
        for (int nt = 0; nt < 4; nt++)
#pragma unroll
            for (int q = 0; q < 4; q++) c[mt][nt][q] = 0.0f;

    // per-lane fragment row indices
    const int arow_base = wm + l7 + l8 * 8;      // + mt*16
    const int brow_base = l7 + l8 * 8;           // + k0

#pragma unroll
    for (int ks = 0; ks < 8; ks++) {
        uint32_t a[2][4];
#pragma unroll
        for (int mt = 0; mt < 2; mt++) {
            int r = arow_base + mt * 16;
            int chunk = ((ks << 1) | l16) ^ (r & 7);
            ldsm_x4(a[mt][0], a[mt][1], a[mt][2], a[mt][3],
                    smA_u + r * 256 + (chunk << 4));
        }
        uint32_t b[2][4];
#pragma unroll
        for (int nh = 0; nh < 2; nh++) {
            int kr = ks * 16 + brow_base;
            int nchunk = ((wn >> 3) + nh * 2 + l16) ^ (kr & 7);
            ldsm_x4_t(b[nh][0], b[nh][1], b[nh][2], b[nh][3],
                      smW_u + kr * 256 + (nchunk << 4));
        }
#pragma unroll
        for (int nh = 0; nh < 2; nh++)
#pragma unroll
            for (int half = 0; half < 2; half++) {
                int nt = nh * 2 + half;
                uint32_t b0 = b[nh][half * 2];
                uint32_t b1 = b[nh][half * 2 + 1];
#pragma unroll
                for (int mt = 0; mt < 2; mt++) {
                    asm volatile(
                        "mma.sync.aligned.m16n8k16.row.col.f32.f16.f16.f32 "
                        "{%0,%1,%2,%3}, {%4,%5,%6,%7}, {%8,%9}, {%0,%1,%2,%3};"
                        : "+f"(c[mt][nt][0]), "+f"(c[mt][nt][1]),
                          "+f"(c[mt][nt][2]), "+f"(c[mt][nt][3])
                        : "r"(a[mt][0]), "r"(a[mt][1]), "r"(a[mt][2]), "r"(a[mt][3]),
                          "r"(b0), "r"(b1));
                }
            }
    }

    // Epilogue: dv = rsqrt(deg+1) inline, pack to fp16 pairs
#pragma unroll
    for (int mt = 0; mt < 2; mt++) {
        int r0 = block_row + wm + mt * 16 + lq;
        int r1 = r0 + 8;
        if (r0 < N_NODES) {
            float s = rsqrtf((float)g_cursor[r0] + 1.0f);
#pragma unroll
            for (int nt = 0; nt < 4; nt++) {
                __half2 p = __floats2half2_rn(c[mt][nt][0] * s, c[mt][nt][1] * s);
                g_G16[(size_t)r0 * (CH / 2) + (wn >> 1) + nt * 4 + lr] = p;
            }
        }
        if (r1 < N_NODES) {
            float s = rsqrtf((float)g_cursor[r1] + 1.0f);
#pragma unroll
            for (int nt = 0; nt < 4; nt++) {
                __half2 p = __floats2half2_rn(c[mt][nt][2] * s, c[mt][nt][3] * s);
                g_G16[(size_t)r1 * (CH / 2) + (wn >> 1) + nt * 4 + lr] = p;
            }
        }
    }
}

// ---------------- Aggregation ----------------
// H[i] = tanh(dv_i*(g16_i + sum_j g16_j) + b),  g16_k = dv_k*G_k
template <bool LAST>
__global__ __launch_bounds__(256)
void agg_kernel_t(const float* __restrict__ b,
                  const float* __restrict__ Wl, const float* __restrict__ bl) {
    const int lane = threadIdx.x & 31;
    const int warp = (blockIdx.x * blockDim.x + threadIdx.x) >> 5;
    if (warp >= N_NODES) return;
    const int i = warp;

    const int cur = g_cursor[i];
    const float dv = rsqrtf((float)cur + 1.0f);
    int deg = cur > MAX_DEG ? MAX_DEG : cur;

    const uint2* Gb = (const uint2*)g_G16;
    uint2 sv = __ldg(Gb + (size_t)i * 32 + lane);   // 32 uint2 per row
    float2 f0 = __half22float2(*(__half2*)&sv.x);
    float2 f1 = __half22float2(*(__half2*)&sv.y);
    float4 acc = make_float4(f0.x, f0.y, f1.x, f1.y);

    const int* bk = g_bucket + (size_t)i * MAX_DEG;

    for (int j = 0; j < deg; j += 8) {
        int4 ia = *(const int4*)(bk + j);         // in-row over-read safe (row=96)
        int4 ib = *(const int4*)(bk + j + 4);
        int s[8] = {ia.x, ia.y, ia.z, ia.w, ib.x, ib.y, ib.z, ib.w};
        uint2 v[8];
#pragma unroll
        for (int q = 0; q < 8; q++) {
            v[q] = (j + q < deg) ? __ldg(Gb + (size_t)s[q] * 32 + lane)
                                 : make_uint2(0u, 0u);   // half2 zeros
        }
#pragma unroll
        for (int q = 0; q < 8; q++) {
            float2 a0 = __half22float2(*(__half2*)&v[q].x);
            float2 a1 = __half22float2(*(__half2*)&v[q].y);
            acc.x += a0.x; acc.y += a0.y; acc.z += a1.x; acc.w += a1.y;
        }
    }

    float4 bb = *(const float4*)(b + lane * 4);
    float4 o;
    o.x = tanhf(fmaf(dv, acc.x, bb.x));
    o.y = tanhf(fmaf(dv, acc.y, bb.y));
    o.z = tanhf(fmaf(dv, acc.z, bb.z));
    o.w = tanhf(fmaf(dv, acc.w, bb.w));

    if (!LAST) {
        uint2 st;
        *(__half2*)&st.x = __floats2half2_rn(o.x, o.y);
        *(__half2*)&st.y = __floats2half2_rn(o.z, o.w);
        *((uint2*)g_H16 + (size_t)i * 32 + lane) = st;
    } else {
        int k = lane * 4;
#pragma unroll
        for (int cidx = 0; cidx < OUT_CH; cidx++) {
            float p = o.x * Wl[(k + 0) * OUT_CH + cidx]
                    + o.y * Wl[(k + 1) * OUT_CH + cidx]
                    + o.z * Wl[(k + 2) * OUT_CH + cidx]
                    + o.w * Wl[(k + 3) * OUT_CH + cidx];
#pragma unroll
            for (int off = 16; off > 0; off >>= 1)
                p += __shfl_xor_sync(0xffffffffu, p, off);
            if (lane == 0) g_H6[(size_t)i * OUT_CH + cidx] = tanhf(p + bl[cidx]);
        }
    }
}

// ---------------- Pool ----------------
__global__ __launch_bounds__(256)
void pool_kernel(float* __restrict__ out) {
    const int g = blockIdx.x;
    __shared__ int s_lo, s_hi;
    __shared__ float ssum[OUT_CH];
    if (threadIdx.x == 0) {
        int lo = 0, hi = N_NODES;
        while (lo < hi) { int m = (lo + hi) >> 1; if (g_batch[m] < g) lo = m + 1; else hi = m; }
        s_lo = lo;
        int lo2 = lo, hi2 = N_NODES;
        while (lo2 < hi2) { int m = (lo2 + hi2) >> 1; if (g_batch[m] < g + 1) lo2 = m + 1; else hi2 = m; }
        s_hi = lo2;
    }
    if (threadIdx.x < OUT_CH) ssum[threadIdx.x] = 0.0f;
    __syncthreads();
    int lo = s_lo, hi = s_hi;
    float loc[OUT_CH];
#pragma unroll
    for (int c = 0; c < OUT_CH; c++) loc[c] = 0.0f;
    for (int i = lo + threadIdx.x; i < hi; i += blockDim.x) {
#pragma unroll
        for (int c = 0; c < OUT_CH; c++) loc[c] += g_H6[(size_t)i * OUT_CH + c];
    }
#pragma unroll
    for (int c = 0; c < OUT_CH; c++) {
#pragma unroll
        for (int off = 16; off > 0; off >>= 1)
            loc[c] += __shfl_xor_sync(0xffffffffu, loc[c], off);
    }
    if ((threadIdx.x & 31) == 0) {
#pragma unroll
        for (int c = 0; c < OUT_CH; c++) atomicAdd(&ssum[c], loc[c]);
    }
    __syncthreads();
    if (threadIdx.x < OUT_CH) {
        float cnt = (float)(hi - lo);
        if (cnt < 1.0f) cnt = 1.0f;
        out[g * OUT_CH + threadIdx.x] = ssum[threadIdx.x] / cnt;
    }
}

// ---------------- launch ----------------
extern "C" void kernel_launch(void* const* d_in, const int* in_sizes, int n_in,
                              void* d_out, int out_size) {
    const float* x   = (const float*)d_in[0];
    const void*  ei  = d_in[1];
    const void*  bat = d_in[2];
    const float* W0  = (const float*)d_in[3];
    const float* b0  = (const float*)d_in[4];
    const float* W1  = (const float*)d_in[5];
    const float* b1  = (const float*)d_in[6];
    const float* W2  = (const float*)d_in[7];
    const float* b2  = (const float*)d_in[8];
    const float* Wl  = (const float*)d_in[9];
    const float* bl  = (const float*)d_in[10];
    float* out = (float*)d_out;

    __half* Wpk;
    cudaGetSymbolAddress((void**)&Wpk, g_Wpk16);

    cudaFuncSetAttribute(gemm_fp16_kernel<false>,
                         cudaFuncAttributeMaxDynamicSharedMemorySize,
                         GEMM_SMEM_BYTES);
    cudaFuncSetAttribute(gemm_fp16_kernel<true>,
                         cudaFuncAttributeMaxDynamicSharedMemorySize,
                         GEMM_SMEM_BYTES);

    zero_detect_kernel<<<(N_NODES + 255) / 256, 256>>>((const unsigned int*)ei);
    packW_all_kernel<<<192, 256>>>(W0, W1, W2);
    convfill_kernel<<<(N_EDGES + 255) / 256, 256>>>(ei, bat);

    const int gemm_grid = (N_NODES + TILE_M - 1) / TILE_M;   // 782
    const int agg_grid  = (N_NODES * 32 + 255) / 256;

    gemm_fp16_kernel<false><<<gemm_grid, 256, GEMM_SMEM_BYTES>>>(x, Wpk);
    agg_kernel_t<false><<<agg_grid, 256>>>(b0, Wl, bl);
    gemm_fp16_kernel<true><<<gemm_grid, 256, GEMM_SMEM_BYTES>>>(nullptr, Wpk + 128 * 128);
    agg_kernel_t<false><<<agg_grid, 256>>>(b1, Wl, bl);
    gemm_fp16_kernel<true><<<gemm_grid, 256, GEMM_SMEM_BYTES>>>(nullptr, Wpk + 2 * 128 * 128);
    agg_kernel_t<true><<<agg_grid, 256>>>(b2, Wl, bl);

    pool_kernel<<<N_GRAPHS, 256>>>(out);
}